// round 15
// baseline (speedup 1.0000x reference)
#include <cuda_runtime.h>
#include <cuda_bf16.h>
#include <cstdint>
#include <cstddef>

#define NN 50000
#define NE 600000
#define D 128
#define BN_EPS 1e-5f

// ---------------- scratch (device globals) -------------------------------------
__device__ float g_h[NN * D];                 // post-BN node features (fp32)
__device__ __nv_bfloat16 g_agg_hi[NN * D];    // aggregate, bf16 split
__device__ __nv_bfloat16 g_agg_lo[NN * D];
__device__ __nv_bfloat16 g_mid_hi[NN * 2 * D];
__device__ __nv_bfloat16 g_mid_lo[NN * 2 * D];
__device__ float g_h2[NN * D];                // pre-BN layer output (fp32)
__device__ float g_sumL[5 * D];               // per-layer column sums
__device__ float g_sumsqL[5 * D];
// pre-split transposed weights
__device__ __nv_bfloat16 g_wt1_hi[5 * 256 * 128];
__device__ __nv_bfloat16 g_wt1_lo[5 * 256 * 128];
__device__ __nv_bfloat16 g_wt2_hi[5 * 128 * 256];
__device__ __nv_bfloat16 g_wt2_lo[5 * 128 * 256];
// CSR structures
__device__ int   g_cnt[NN];
__device__ int   g_rowstart[NN + 1];
__device__ int   g_cursor[NN];
__device__ int   g_edges[NE];                 // src | (combo << 16)
__device__ float g_eec[5 * 24 * D];           // all layers precomputed

// ---------------- helpers -------------------------------------------------------
__device__ __forceinline__ uint32_t pack2bf(float x, float y) {
    __nv_bfloat162 h = __floats2bfloat162_rn(x, y);
    return *(uint32_t*)&h;
}
__device__ __forceinline__ void split2(float x, float y,
                                       uint32_t& hi, uint32_t& lo) {
    __nv_bfloat16 hx = __float2bfloat16(x);
    __nv_bfloat16 hy = __float2bfloat16(y);
    float rx = x - __bfloat162float(hx);
    float ry = y - __bfloat162float(hy);
    __nv_bfloat162 h2 = __halves2bfloat162(hx, hy);
    hi = *(uint32_t*)&h2;
    lo = pack2bf(rx, ry);
}
__device__ __forceinline__ void cp_async16(void* dst, const void* src,
                                           int src_bytes) {
    uint32_t d = (uint32_t)__cvta_generic_to_shared(dst);
    asm volatile("cp.async.cg.shared.global [%0], [%1], 16, %2;\n"
                 :: "r"(d), "l"(src), "r"(src_bytes));
}
#define CP_COMMIT() asm volatile("cp.async.commit_group;\n" ::: "memory")
#define CP_WAIT(n)  asm volatile("cp.async.wait_group %0;\n" :: "n"(n) : "memory")

#define LDSM4(r, addr)                                                    \
    asm volatile("ldmatrix.sync.aligned.m8n8.x4.shared.b16 "              \
                 "{%0,%1,%2,%3}, [%4];"                                   \
                 : "=r"((r)[0]), "=r"((r)[1]), "=r"((r)[2]), "=r"((r)[3]) \
                 : "r"(addr))

#define MMA_BF16(acc, a, b)                                              \
    asm volatile(                                                        \
        "mma.sync.aligned.m16n8k16.row.col.f32.bf16.bf16.f32 "           \
        "{%0,%1,%2,%3}, {%4,%5,%6,%7}, {%8,%9}, {%0,%1,%2,%3};\n"        \
        : "+f"(acc[0]), "+f"(acc[1]), "+f"(acc[2]), "+f"(acc[3])         \
        : "r"(a[0]), "r"(a[1]), "r"(a[2]), "r"(a[3]),                    \
          "r"(b[0]), "r"(b[1]))

// ---------------- input embedding ---------------------------------------------
__global__ void embed_kernel(const int* __restrict__ x,
                             const float* __restrict__ atom,
                             const float* __restrict__ chir,
                             const float* __restrict__ hyb) {
    int t = blockIdx.x * blockDim.x + threadIdx.x;
    int node = t >> 5, lane = t & 31;
    if (node >= NN) return;
    int x0 = x[node * 3 + 0];
    int x1 = x[node * 3 + 1];
    int x2 = x[node * 3 + 2];
    float4 a = ((const float4*)(atom + (size_t)x0 * D))[lane];
    float4 c = ((const float4*)(chir + (size_t)x1 * D))[lane];
    float4 y = ((const float4*)(hyb  + (size_t)x2 * D))[lane];
    ((float4*)g_h)[(size_t)node * 32 + lane] =
        make_float4(a.x + c.x + y.x, a.y + c.y + y.y,
                    a.z + c.z + y.z, a.w + c.w + y.w);
}

// ---------------- weight prep: transpose + bf16 split --------------------------
__global__ void wprep_kernel(const float* __restrict__ W1,
                             const float* __restrict__ W2) {
    int t = blockIdx.x * blockDim.x + threadIdx.x;
    int total = 5 * 128 * 256;
    if (t < total) {
        int l = t / (128 * 256);
        int r = t % (128 * 256);
        int k = r / 256, n = r % 256;
        float v = W1[t];
        __nv_bfloat16 h = __float2bfloat16(v);
        g_wt1_hi[l * 32768 + n * 128 + k] = h;
        g_wt1_lo[l * 32768 + n * 128 + k] =
            __float2bfloat16(v - __bfloat162float(h));
    } else if (t < 2 * total) {
        int u = t - total;
        int l = u / (256 * 128);
        int r = u % (256 * 128);
        int k = r / 128, n = r % 128;
        float v = W2[u];
        __nv_bfloat16 h = __float2bfloat16(v);
        g_wt2_hi[l * 32768 + n * 256 + k] = h;
        g_wt2_lo[l * 32768 + n * 256 + k] =
            __float2bfloat16(v - __bfloat162float(h));
    }
}

// ---------------- CSR build ----------------------------------------------------
__global__ void count_kernel(const int* __restrict__ ei) {
    int e = blockIdx.x * blockDim.x + threadIdx.x;
    if (e >= NE) return;
    atomicAdd(&g_cnt[ei[NE + e]], 1);
}

__global__ void scan_kernel() {
    __shared__ int warpsum[32];
    __shared__ int carry;
    int lane = threadIdx.x & 31, wid = threadIdx.x >> 5;
    if (threadIdx.x == 0) carry = 0;
    __syncthreads();
    for (int base = 0; base < NN; base += 1024) {
        int i = base + threadIdx.x;
        int v = (i < NN) ? g_cnt[i] : 0;
        int xs = v;
#pragma unroll
        for (int off = 1; off < 32; off <<= 1) {
            int t = __shfl_up_sync(0xffffffff, xs, off);
            if (lane >= off) xs += t;
        }
        if (lane == 31) warpsum[wid] = xs;
        __syncthreads();
        if (wid == 0) {
            int w = warpsum[lane];
#pragma unroll
            for (int off = 1; off < 32; off <<= 1) {
                int t = __shfl_up_sync(0xffffffff, w, off);
                if (lane >= off) w += t;
            }
            warpsum[lane] = w;
        }
        __syncthreads();
        int wpre = (wid > 0) ? warpsum[wid - 1] : 0;
        int incl = xs + wpre;
        int excl = incl - v + carry;
        if (i < NN) { g_rowstart[i] = excl; g_cursor[i] = excl; }
        __syncthreads();
        if (threadIdx.x == 1023) carry += incl;
        __syncthreads();
    }
    if (threadIdx.x == 0) g_rowstart[NN] = carry;
}

__global__ void fill_kernel(const int* __restrict__ ei,
                            const int* __restrict__ ea) {
    int e = blockIdx.x * blockDim.x + threadIdx.x;
    if (e >= NE) return;
    int dst = ei[NE + e];
    int pos = atomicAdd(&g_cursor[dst], 1);
    int cb = ea[2 * e] * 4 + ea[2 * e + 1];
    g_edges[pos] = ei[e] | (cb << 16);
}

// ---------------- edge-combo tables for ALL layers ------------------------------
__global__ void eec_kernel(const float* __restrict__ e1,
                           const float* __restrict__ e2) {
    int b = blockIdx.x;            // 0..119 = l*24+cb
    int l = b / 24, cb = b % 24;
    int lane = threadIdx.x;
    int a0 = cb >> 2, a1 = cb & 3;
    float4 v1 = ((const float4*)(e1 + (size_t)l * 6 * D + (size_t)a0 * D))[lane];
    float4 v2 = ((const float4*)(e2 + (size_t)l * 4 * D + (size_t)a1 * D))[lane];
    ((float4*)g_eec)[(l * 24 + cb) * 32 + lane] =
        make_float4(v1.x + v2.x, v1.y + v2.y, v1.z + v2.z, v1.w + v2.w);
}

// ---------------- zero all per-layer stats (once at prep) -----------------------
__global__ void zero_statsL_kernel() {
    int i = blockIdx.x * 128 + threadIdx.x;
    g_sumL[i] = 0.f;
    g_sumsqL[i] = 0.f;
}

// ---------------- gather-aggregate: warp per node (round-11 proven) -------------
__global__ void agg_kernel(const float* __restrict__ h, int layer) {
    int t = blockIdx.x * blockDim.x + threadIdx.x;
    int n = t >> 5, lane = t & 31;
    if (n >= NN) return;
    const float4* eec = ((const float4*)g_eec) + layer * 24 * 32;
    int beg = g_rowstart[n], end = g_rowstart[n + 1];
    float4 acc = make_float4(0.f, 0.f, 0.f, 0.f);
    int i = beg;
    for (; i + 3 < end; i += 4) {
        int p0 = g_edges[i];
        int p1 = g_edges[i + 1];
        int p2 = g_edges[i + 2];
        int p3 = g_edges[i + 3];
        float4 a0 = ((const float4*)h)[(size_t)(p0 & 0xFFFF) * 32 + lane];
        float4 a1 = ((const float4*)h)[(size_t)(p1 & 0xFFFF) * 32 + lane];
        float4 a2 = ((const float4*)h)[(size_t)(p2 & 0xFFFF) * 32 + lane];
        float4 a3 = ((const float4*)h)[(size_t)(p3 & 0xFFFF) * 32 + lane];
        float4 e0 = eec[(p0 >> 16) * 32 + lane];
        float4 e1v = eec[(p1 >> 16) * 32 + lane];
        float4 e2v = eec[(p2 >> 16) * 32 + lane];
        float4 e3v = eec[(p3 >> 16) * 32 + lane];
        acc.x += (a0.x + e0.x) + (a1.x + e1v.x) + (a2.x + e2v.x) + (a3.x + e3v.x);
        acc.y += (a0.y + e0.y) + (a1.y + e1v.y) + (a2.y + e2v.y) + (a3.y + e3v.y);
        acc.z += (a0.z + e0.z) + (a1.z + e1v.z) + (a2.z + e2v.z) + (a3.z + e3v.z);
        acc.w += (a0.w + e0.w) + (a1.w + e1v.w) + (a2.w + e2v.w) + (a3.w + e3v.w);
    }
    for (; i < end; ++i) {
        int p0 = g_edges[i];
        float4 a = ((const float4*)h)[(size_t)(p0 & 0xFFFF) * 32 + lane];
        float4 e0 = eec[(p0 >> 16) * 32 + lane];
        acc.x += a.x + e0.x;
        acc.y += a.y + e0.y;
        acc.z += a.z + e0.z;
        acc.w += a.w + e0.w;
    }
    uint32_t h0, l0, h1, l1;
    split2(acc.x, acc.y, h0, l0);
    split2(acc.z, acc.w, h1, l1);
    ((uint2*)g_agg_hi)[(size_t)n * 32 + lane] = make_uint2(h0, h1);
    ((uint2*)g_agg_lo)[(size_t)n * 32 + lane] = make_uint2(l0, l1);
}

// ---------------- BN apply with inline scale/shift computation -------------------
__global__ void bn_apply_kernel(const float* __restrict__ h2,
                                float* __restrict__ outp, int relu,
                                const float* __restrict__ sum,
                                const float* __restrict__ sumsq,
                                const float* __restrict__ gamma,
                                const float* __restrict__ beta) {
    int t = blockIdx.x * blockDim.x + threadIdx.x;
    int node = t >> 5, lane = t & 31;
    if (node >= NN) return;
    const float inv = 1.0f / (float)NN;
    float4 sm4 = ((const float4*)sum)[lane];
    float4 sq4 = ((const float4*)sumsq)[lane];
    float4 gm = ((const float4*)gamma)[lane];
    float4 bt = ((const float4*)beta)[lane];
    float4 v = ((const float4*)h2)[(size_t)node * 32 + lane];
    float4 o;
    { float mean = sm4.x * inv; float var = sq4.x * inv - mean * mean;
      float s = gm.x * rsqrtf(var + BN_EPS);
      o.x = fmaf(s, v.x, bt.x - mean * s); }
    { float mean = sm4.y * inv; float var = sq4.y * inv - mean * mean;
      float s = gm.y * rsqrtf(var + BN_EPS);
      o.y = fmaf(s, v.y, bt.y - mean * s); }
    { float mean = sm4.z * inv; float var = sq4.z * inv - mean * mean;
      float s = gm.z * rsqrtf(var + BN_EPS);
      o.z = fmaf(s, v.z, bt.z - mean * s); }
    { float mean = sm4.w * inv; float var = sq4.w * inv - mean * mean;
      float s = gm.w * rsqrtf(var + BN_EPS);
      o.w = fmaf(s, v.w, bt.w - mean * s); }
    if (relu) {
        o.x = fmaxf(o.x, 0.f); o.y = fmaxf(o.y, 0.f);
        o.z = fmaxf(o.z, 0.f); o.w = fmaxf(o.w, 0.f);
    }
    ((float4*)outp)[(size_t)node * 32 + lane] = o;
}

// ---------------- GEMM1: bf16x3, BM=BN=128, cp.async + ldmatrix (round-11) ------
#define PAD 40
#define TILE_E (128 * PAD)
#define TILE_B (TILE_E * 2)
#define STAGE_E (4 * TILE_E)
#define SMEM_BYTES (2 * STAGE_E * 2)    // 81920

__global__ __launch_bounds__(256) void gemm1_kernel(
    const __nv_bfloat16* __restrict__ Ah, const __nv_bfloat16* __restrict__ Al,
    const __nv_bfloat16* __restrict__ Bh, const __nv_bfloat16* __restrict__ Bl,
    const float* __restrict__ bias,
    __nv_bfloat16* __restrict__ Ch, __nv_bfloat16* __restrict__ Cl,
    int M, int N, int K) {
    extern __shared__ __nv_bfloat16 smem[];

    const int tid  = threadIdx.x;
    const int warp = tid >> 5, lane = tid & 31;
    const int gid  = lane >> 2;
    const int tig  = lane & 3;
    const int wm   = (warp & 3) * 32;
    const int wn   = (warp >> 2) * 64;
    const int m0   = blockIdx.y * 128;
    const int n0b  = blockIdx.x * 128;

    float acc[2][8][4];
#pragma unroll
    for (int mi = 0; mi < 2; mi++)
#pragma unroll
        for (int ni = 0; ni < 8; ni++)
#pragma unroll
            for (int q = 0; q < 4; q++) acc[mi][ni][q] = 0.f;

    const int sr = tid >> 2;
    const int sc = (tid & 3) * 8;
    const int nchunk = K >> 5;

    uint32_t offA[2];
#pragma unroll
    for (int mi = 0; mi < 2; mi++) {
        int row = wm + mi * 16 + (lane & 15);
        int cg  = lane >> 4;
        offA[mi] = (uint32_t)(row * PAD + cg * 8) * 2;
    }
    uint32_t offB[4];
#pragma unroll
    for (int nj = 0; nj < 4; nj++) {
        int row = wn + nj * 16 + ((lane >> 4) * 8) + (lane & 7);
        int cg  = (lane >> 3) & 1;
        offB[nj] = (uint32_t)(row * PAD + cg * 8) * 2;
    }
    const uint32_t smem_u32 = (uint32_t)__cvta_generic_to_shared(smem);

    auto stage = [&](int c) {
        __nv_bfloat16* buf = smem + (c & 1) * STAGE_E;
        __nv_bfloat16* Ah_s = buf;
        __nv_bfloat16* Al_s = buf + TILE_E;
        __nv_bfloat16* Bh_s = buf + 2 * TILE_E;
        __nv_bfloat16* Bl_s = buf + 3 * TILE_E;
        int k0 = c << 5;
#pragma unroll
        for (int i = 0; i < 2; i++) {
            int r = sr + i * 64;
            bool ok = (m0 + r < M);
            const __nv_bfloat16* sa = ok ? (Ah + (size_t)(m0 + r) * K + k0 + sc) : Ah;
            const __nv_bfloat16* sl = ok ? (Al + (size_t)(m0 + r) * K + k0 + sc) : Al;
            cp_async16(&Ah_s[r * PAD + sc], sa, ok ? 16 : 0);
            cp_async16(&Al_s[r * PAD + sc], sl, ok ? 16 : 0);
            cp_async16(&Bh_s[r * PAD + sc], Bh + (size_t)(n0b + r) * K + k0 + sc, 16);
            cp_async16(&Bl_s[r * PAD + sc], Bl + (size_t)(n0b + r) * K + k0 + sc, 16);
        }
        CP_COMMIT();
    };

    stage(0);

    for (int c = 0; c < nchunk; ++c) {
        if (c + 1 < nchunk) {
            stage(c + 1);
            CP_WAIT(1);
        } else {
            CP_WAIT(0);
        }
        __syncthreads();

        uint32_t sb = smem_u32 + (uint32_t)((c & 1) * STAGE_E * 2);

#pragma unroll
        for (int ks = 0; ks < 2; ks++) {
            const uint32_t kb = ks * 32;
            uint32_t ah[2][4], al[2][4];
            LDSM4(ah[0], sb + offA[0] + kb);
            LDSM4(ah[1], sb + offA[1] + kb);
            LDSM4(al[0], sb + TILE_B + offA[0] + kb);
            LDSM4(al[1], sb + TILE_B + offA[1] + kb);
            uint32_t bh[8][2], bl[8][2];
#pragma unroll
            for (int nj = 0; nj < 4; nj++) {
                uint32_t th[4], tl[4];
                LDSM4(th, sb + 2 * TILE_B + offB[nj] + kb);
                LDSM4(tl, sb + 3 * TILE_B + offB[nj] + kb);
                bh[2 * nj][0] = th[0]; bh[2 * nj][1] = th[1];
                bh[2 * nj + 1][0] = th[2]; bh[2 * nj + 1][1] = th[3];
                bl[2 * nj][0] = tl[0]; bl[2 * nj][1] = tl[1];
                bl[2 * nj + 1][0] = tl[2]; bl[2 * nj + 1][1] = tl[3];
            }
#pragma unroll
            for (int mi = 0; mi < 2; mi++)
#pragma unroll
                for (int ni = 0; ni < 8; ni++) {
                    MMA_BF16(acc[mi][ni], al[mi], bh[ni]);
                    MMA_BF16(acc[mi][ni], ah[mi], bl[ni]);
                    MMA_BF16(acc[mi][ni], ah[mi], bh[ni]);
                }
        }
        __syncthreads();
    }

    // epilogue: bias + relu, bf16 hi/lo split out
#pragma unroll
    for (int mi = 0; mi < 2; mi++) {
        int r0 = m0 + wm + mi * 16 + gid;
#pragma unroll
        for (int ni = 0; ni < 8; ni++) {
            int gc = n0b + wn + ni * 8 + 2 * tig;
            float bv0 = bias[gc], bv1 = bias[gc + 1];
            float v0 = fmaxf(acc[mi][ni][0] + bv0, 0.f);
            float v1 = fmaxf(acc[mi][ni][1] + bv1, 0.f);
            float v2 = fmaxf(acc[mi][ni][2] + bv0, 0.f);
            float v3 = fmaxf(acc[mi][ni][3] + bv1, 0.f);
            uint32_t h0, l0, h1, l1;
            split2(v0, v1, h0, l0);
            split2(v2, v3, h1, l1);
            if (r0 < M) {
                *(uint32_t*)(Ch + (size_t)r0 * N + gc) = h0;
                *(uint32_t*)(Cl + (size_t)r0 * N + gc) = l0;
            }
            if (r0 + 8 < M) {
                *(uint32_t*)(Ch + (size_t)(r0 + 8) * N + gc) = h1;
                *(uint32_t*)(Cl + (size_t)(r0 + 8) * N + gc) = l1;
            }
        }
    }
}

// ---------------- GEMM2: bf16x3, BM=64, N=128, K=256, fused stats ----------------
#define PAD2 40
#define A2T_E (64 * PAD2)                   // 2560 elems
#define B2T_E (128 * PAD2)                  // 5120 elems
#define A2T_B (A2T_E * 2)
#define B2T_B (B2T_E * 2)
#define ST2_E (2 * A2T_E + 2 * B2T_E)       // 15360 elems
#define SM2_BYTES (2 * ST2_E * 2)           // 61440 bytes

__global__ __launch_bounds__(256) void gemm2_kernel(
    const __nv_bfloat16* __restrict__ Ah, const __nv_bfloat16* __restrict__ Al,
    const __nv_bfloat16* __restrict__ Bh, const __nv_bfloat16* __restrict__ Bl,
    const float* __restrict__ bias, float* __restrict__ Cf,
    float* __restrict__ psum, float* __restrict__ psumsq) {
    extern __shared__ __nv_bfloat16 smem[];
    const int K = 256, N = 128;

    const int tid  = threadIdx.x;
    const int warp = tid >> 5, lane = tid & 31;
    const int gid  = lane >> 2;
    const int tig  = lane & 3;
    const int wm   = (warp & 1) * 32;         // 2 m-groups
    const int wn   = (warp >> 1) * 32;        // 4 n-groups of 32
    const int m0   = blockIdx.x * 64;

    float acc[2][4][4];
#pragma unroll
    for (int mi = 0; mi < 2; mi++)
#pragma unroll
        for (int ni = 0; ni < 4; ni++)
#pragma unroll
            for (int q = 0; q < 4; q++) acc[mi][ni][q] = 0.f;

    const int sr = tid >> 2;            // 0..63
    const int sc = (tid & 3) * 8;

    uint32_t offA[2];
#pragma unroll
    for (int mi = 0; mi < 2; mi++) {
        int row = wm + mi * 16 + (lane & 15);     // < 64
        int cg  = lane >> 4;
        offA[mi] = (uint32_t)(row * PAD2 + cg * 8) * 2;
    }
    uint32_t offB[2];
#pragma unroll
    for (int nj = 0; nj < 2; nj++) {
        int row = wn + nj * 16 + ((lane >> 4) * 8) + (lane & 7);  // < 128
        int cg  = (lane >> 3) & 1;
        offB[nj] = (uint32_t)(row * PAD2 + cg * 8) * 2;
    }
    const uint32_t smem_u32 = (uint32_t)__cvta_generic_to_shared(smem);

    auto stage = [&](int c) {
        __nv_bfloat16* buf = smem + (c & 1) * ST2_E;
        __nv_bfloat16* Ah_s = buf;
        __nv_bfloat16* Al_s = buf + A2T_E;
        __nv_bfloat16* Bh_s = buf + 2 * A2T_E;
        __nv_bfloat16* Bl_s = buf + 2 * A2T_E + B2T_E;
        int k0 = c << 5;
        {
            int r = sr;                              // 0..63 (A rows)
            bool ok = (m0 + r < NN);
            const __nv_bfloat16* sa = ok ? (Ah + (size_t)(m0 + r) * K + k0 + sc) : Ah;
            const __nv_bfloat16* sl = ok ? (Al + (size_t)(m0 + r) * K + k0 + sc) : Al;
            cp_async16(&Ah_s[r * PAD2 + sc], sa, ok ? 16 : 0);
            cp_async16(&Al_s[r * PAD2 + sc], sl, ok ? 16 : 0);
        }
#pragma unroll
        for (int i = 0; i < 2; i++) {
            int r = sr + i * 64;                     // 0..127 (B rows)
            cp_async16(&Bh_s[r * PAD2 + sc], Bh + (size_t)r * K + k0 + sc, 16);
            cp_async16(&Bl_s[r * PAD2 + sc], Bl + (size_t)r * K + k0 + sc, 16);
        }
        CP_COMMIT();
    };

    stage(0);

    for (int c = 0; c < K / 32; ++c) {
        if (c + 1 < K / 32) {
            stage(c + 1);
            CP_WAIT(1);
        } else {
            CP_WAIT(0);
        }
        __syncthreads();

        uint32_t sb = smem_u32 + (uint32_t)((c & 1) * ST2_E * 2);

#pragma unroll
        for (int ks = 0; ks < 2; ks++) {
            const uint32_t kb = ks * 32;
            uint32_t ah[2][4], al[2][4];
            LDSM4(ah[0], sb + offA[0] + kb);
            LDSM4(ah[1], sb + offA[1] + kb);
            LDSM4(al[0], sb + A2T_B + offA[0] + kb);
            LDSM4(al[1], sb + A2T_B + offA[1] + kb);
            uint32_t bh[4][2], bl[4][2];
#pragma unroll
            for (int nj = 0; nj < 2; nj++) {
                uint32_t th[4], tl[4];
                LDSM4(th, sb + 2 * A2T_B + offB[nj] + kb);
                LDSM4(tl, sb + 2 * A2T_B + B2T_B + offB[nj] + kb);
                bh[2 * nj][0] = th[0]; bh[2 * nj][1] = th[1];
                bh[2 * nj + 1][0] = th[2]; bh[2 * nj + 1][1] = th[3];
                bl[2 * nj][0] = tl[0]; bl[2 * nj][1] = tl[1];
                bl[2 * nj + 1][0] = tl[2]; bl[2 * nj + 1][1] = tl[3];
            }
#pragma unroll
            for (int mi = 0; mi < 2; mi++)
#pragma unroll
                for (int ni = 0; ni < 4; ni++) {
                    MMA_BF16(acc[mi][ni], al[mi], bh[ni]);
                    MMA_BF16(acc[mi][ni], ah[mi], bl[ni]);
                    MMA_BF16(acc[mi][ni], ah[mi], bh[ni]);
                }
        }
        __syncthreads();
    }

    // epilogue: bias, fp32 store, fused per-column stats
    float ls[8], ls2[8];
#pragma unroll
    for (int j = 0; j < 8; j++) { ls[j] = 0.f; ls2[j] = 0.f; }

#pragma unroll
    for (int mi = 0; mi < 2; mi++) {
        int r0 = m0 + wm + mi * 16 + gid;
#pragma unroll
        for (int ni = 0; ni < 4; ni++) {
            int gc = wn + ni * 8 + 2 * tig;
            float bv0 = bias[gc], bv1 = bias[gc + 1];
            float v0 = acc[mi][ni][0] + bv0;
            float v1 = acc[mi][ni][1] + bv1;
            float v2 = acc[mi][ni][2] + bv0;
            float v3 = acc[mi][ni][3] + bv1;
            bool ok0 = (r0 < NN), ok1 = (r0 + 8 < NN);
            if (ok0) {
                *(float2*)(Cf + (size_t)r0 * N + gc) = make_float2(v0, v1);
                ls[ni * 2]     += v0; ls2[ni * 2]     += v0 * v0;
                ls[ni * 2 + 1] += v1; ls2[ni * 2 + 1] += v1 * v1;
            }
            if (ok1) {
                *(float2*)(Cf + (size_t)(r0 + 8) * N + gc) = make_float2(v2, v3);
                ls[ni * 2]     += v2; ls2[ni * 2]     += v2 * v2;
                ls[ni * 2 + 1] += v3; ls2[ni * 2 + 1] += v3 * v3;
            }
        }
    }

#pragma unroll
    for (int j = 0; j < 8; j++) {
#pragma unroll
        for (int off = 4; off < 32; off <<= 1) {
            ls[j]  += __shfl_xor_sync(0xffffffff, ls[j], off);
            ls2[j] += __shfl_xor_sync(0xffffffff, ls2[j], off);
        }
    }
    float* cs  = (float*)smem;
    float* cs2 = (float*)smem + 128;
    if (tid < 128) { cs[tid] = 0.f; cs2[tid] = 0.f; }
    __syncthreads();
    if (lane < 4) {
#pragma unroll
        for (int ni = 0; ni < 4; ni++) {
            int c0 = wn + ni * 8 + 2 * lane;
            atomicAdd(&cs[c0],      ls[ni * 2]);
            atomicAdd(&cs2[c0],     ls2[ni * 2]);
            atomicAdd(&cs[c0 + 1],  ls[ni * 2 + 1]);
            atomicAdd(&cs2[c0 + 1], ls2[ni * 2 + 1]);
        }
    }
    __syncthreads();
    if (tid < 128) {
        atomicAdd(&psum[tid],   cs[tid]);
        atomicAdd(&psumsq[tid], cs2[tid]);
    }
}

// ---------------- launch --------------------------------------------------------
extern "C" void kernel_launch(void* const* d_in, const int* in_sizes, int n_in,
                              void* d_out, int out_size) {
    const int*   x     = (const int*)d_in[0];
    const int*   ei    = (const int*)d_in[1];
    const int*   ea    = (const int*)d_in[2];
    const float* atom  = (const float*)d_in[3];
    const float* chir  = (const float*)d_in[4];
    const float* hyb   = (const float*)d_in[5];
    const float* e1    = (const float*)d_in[6];
    const float* e2    = (const float*)d_in[7];
    const float* W1    = (const float*)d_in[8];
    const float* b1    = (const float*)d_in[9];
    const float* W2    = (const float*)d_in[10];
    const float* b2    = (const float*)d_in[11];
    const float* gamma = (const float*)d_in[12];
    const float* beta  = (const float*)d_in[13];
    float* out = (float*)d_out;

    float *p_h, *p_h2, *p_sumL, *p_sumsqL;
    int* p_cnt;
    __nv_bfloat16 *p_agg_hi, *p_agg_lo, *p_mid_hi, *p_mid_lo;
    __nv_bfloat16 *p_wt1_hi, *p_wt1_lo, *p_wt2_hi, *p_wt2_lo;
    cudaGetSymbolAddress((void**)&p_h,       g_h);
    cudaGetSymbolAddress((void**)&p_h2,      g_h2);
    cudaGetSymbolAddress((void**)&p_cnt,     g_cnt);
    cudaGetSymbolAddress((void**)&p_sumL,    g_sumL);
    cudaGetSymbolAddress((void**)&p_sumsqL,  g_sumsqL);
    cudaGetSymbolAddress((void**)&p_agg_hi,  g_agg_hi);
    cudaGetSymbolAddress((void**)&p_agg_lo,  g_agg_lo);
    cudaGetSymbolAddress((void**)&p_mid_hi,  g_mid_hi);
    cudaGetSymbolAddress((void**)&p_mid_lo,  g_mid_lo);
    cudaGetSymbolAddress((void**)&p_wt1_hi,  g_wt1_hi);
    cudaGetSymbolAddress((void**)&p_wt1_lo,  g_wt1_lo);
    cudaGetSymbolAddress((void**)&p_wt2_hi,  g_wt2_hi);
    cudaGetSymbolAddress((void**)&p_wt2_lo,  g_wt2_lo);

    cudaFuncSetAttribute(gemm1_kernel,
                         cudaFuncAttributeMaxDynamicSharedMemorySize, SMEM_BYTES);
    cudaFuncSetAttribute(gemm2_kernel,
                         cudaFuncAttributeMaxDynamicSharedMemorySize, SM2_BYTES);

    const int TPB = 256;
    const int node_blocks = (NN * 32 + TPB - 1) / TPB;
    const int edge_blocks = (NE + TPB - 1) / TPB;
    const int mrows = (NN + 127) / 128;
    const int m2rows = (NN + 63) / 64;

    // one-time prep (layer-invariant)
    cudaMemsetAsync(p_cnt, 0, NN * sizeof(int));
    zero_statsL_kernel<<<5, 128>>>();
    count_kernel<<<edge_blocks, TPB>>>(ei);
    scan_kernel<<<1, 1024>>>();
    fill_kernel<<<edge_blocks, TPB>>>(ei, ea);
    wprep_kernel<<<(2 * 5 * 128 * 256 + TPB - 1) / TPB, TPB>>>(W1, W2);
    eec_kernel<<<120, 32>>>(e1, e2);
    embed_kernel<<<node_blocks, TPB>>>(x, atom, chir, hyb);

    for (int l = 0; l < 5; ++l) {
        agg_kernel<<<node_blocks, TPB>>>(p_h, l);
        // Linear1 + ReLU -> mid (bf16 hi/lo)
        gemm1_kernel<<<dim3(2, mrows), 256, SMEM_BYTES>>>(
            p_agg_hi, p_agg_lo,
            p_wt1_hi + (size_t)l * 32768, p_wt1_lo + (size_t)l * 32768,
            b1 + (size_t)l * 2 * D,
            p_mid_hi, p_mid_lo,
            NN, 2 * D, D);
        // Linear2 -> h2 (fp32) with fused column stats (per-layer slots)
        gemm2_kernel<<<m2rows, 256, SM2_BYTES>>>(
            p_mid_hi, p_mid_lo,
            p_wt2_hi + (size_t)l * 32768, p_wt2_lo + (size_t)l * 32768,
            b2 + (size_t)l * D, p_h2,
            p_sumL + (size_t)l * D, p_sumsqL + (size_t)l * D);
        // BN apply (inline scale/shift from per-layer stats)
        bn_apply_kernel<<<node_blocks, TPB>>>(
            p_h2, (l == 4) ? out : p_h, (l < 4) ? 1 : 0,
            p_sumL + (size_t)l * D, p_sumsqL + (size_t)l * D,
            gamma + (size_t)l * D, beta + (size_t)l * D);
    }
}